// round 16
// baseline (speedup 1.0000x reference)
#include <cuda_runtime.h>
#include <cuda_fp16.h>
#include <cstdint>

#define B_  8
#define N_  2048
#define M_  2048
#define D_  512
#define H_  8
#define BH_ (B_ * H_)
#define HD_ (H_ * D_)

// -------------------------------------------------------------------------
// Device scratch — all GEMM operands fp16 hi-only (1-pass scheme).
// -------------------------------------------------------------------------
__device__ __half g_kc_hi[(size_t)B_ * N_ * D_];
__device__ __half g_vc_hi[(size_t)B_ * N_ * D_];
__device__ __half g_qc_hi[(size_t)B_ * M_ * D_];
__device__ __half g_WkT_hi[(size_t)H_ * D_ * D_];
__device__ __half g_WvT_hi[(size_t)H_ * D_ * D_];
__device__ __half g_WqT_hi[(size_t)H_ * D_ * D_];
__device__ __half g_WoP_hi[(size_t)D_ * HD_];        // [n=512][k=h*512+d]
__device__ __half g_kp_hi[(size_t)BH_ * N_ * D_];    // k'
__device__ __half g_qp_hi[(size_t)BH_ * M_ * D_];    // q'
__device__ __half g_vT_hi[(size_t)BH_ * D_ * N_];    // v'^T
__device__ float  g_scores[(size_t)BH_ * M_ * N_];
__device__ __half g_P_hi[(size_t)BH_ * M_ * N_];     // softmax probs
__device__ __half g_at_hi[(size_t)BH_ * M_ * D_];    // attn out [z][m][d]

// -------------------------------------------------------------------------
// PTX helpers (family-baseline instructions only)
// -------------------------------------------------------------------------
__device__ __forceinline__ uint32_t smem_to_u32(const void* p) {
    uint32_t a;
    asm("{ .reg .u64 t; cvta.to.shared.u64 t, %1; cvt.u32.u64 %0, t; }" : "=r"(a) : "l"(p));
    return a;
}
__device__ __forceinline__ void cp16(uint32_t dst, const void* src) {
    asm volatile("cp.async.cg.shared.global [%0], [%1], 16;" :: "r"(dst), "l"(src));
}
#define CP_COMMIT() asm volatile("cp.async.commit_group;" ::: "memory")
#define CP_WAIT2()  asm volatile("cp.async.wait_group 2;" ::: "memory")

__device__ __forceinline__ void ldsm4(uint32_t* r, uint32_t addr) {
    asm volatile("ldmatrix.sync.aligned.m8n8.x4.shared.b16 {%0,%1,%2,%3}, [%4];"
                 : "=r"(r[0]), "=r"(r[1]), "=r"(r[2]), "=r"(r[3]) : "r"(addr));
}
__device__ __forceinline__ void mma16816(float* c, const uint32_t* a,
                                         uint32_t b0, uint32_t b1) {
    asm volatile("mma.sync.aligned.m16n8k16.row.col.f32.f16.f16.f32 "
                 "{%0,%1,%2,%3}, {%4,%5,%6,%7}, {%8,%9}, {%0,%1,%2,%3};"
                 : "+f"(c[0]), "+f"(c[1]), "+f"(c[2]), "+f"(c[3])
                 : "r"(a[0]), "r"(a[1]), "r"(a[2]), "r"(a[3]), "r"(b0), "r"(b1));
}

// -------------------------------------------------------------------------
// 1-pass fp16 tensor-core GEMM.  C[z] = alpha * A[z] @ B[z]^T (+ bias)
// A: [Md, Kd] fp16 row-major.  B: [Nd, Kd] fp16 K-major.
// EPI: 0 = fp32 out; 2 = fp16 transposed out (C[n*Md+m]); 3 = fp16 row-major.
// GA:  gather A from attention layout [h][m][d], k = h*512 + d.
// CTA tile 128(M) x 256(N), BK=64, 256 threads (2x4 warps), warp tile 64x64.
// 4-stage cp.async ring (lookahead 3, one barrier/iter) + double-buffered
// register fragments: kc+1's ldsm issue while kc's MMAs execute, so MMAs
// never wait on same-kc ldsm latency.
// Stage = A(16K) + B(32K) = 48KB; 4 stages = 192KB.
// -------------------------------------------------------------------------
#define STAGE_BYTES 49152u
#define SHM_TOTAL   (4 * 49152)

template <int EPI, bool GA>
__global__ void __launch_bounds__(256, 1) hgemm_kernel(
    const __half* __restrict__ Ah, const __half* __restrict__ Bh,
    float* __restrict__ Cf, __half* __restrict__ Ch,
    int Md, int Nd, int Kd, int divA, int modB,
    long long strideA, long long strideB, long long strideC,
    float alpha, const float* __restrict__ bias, int biasStride)
{
    extern __shared__ char smem[];
    const uint32_t sm0 = smem_to_u32(smem);
    const int tid = threadIdx.x;
    const int wid = tid >> 5, lane = tid & 31;
    const int wm = wid >> 2, wn = wid & 3;           // 2(M) x 4(N) warp grid

    const int z = blockIdx.z;
    Ah += (long long)(z / divA) * strideA;
    Bh += (long long)(z % modB) * strideB;
    const long long coff = (long long)z * strideC;
    const float* bptr = bias ? (bias + (long long)(z % modB) * biasStride) : nullptr;
    const int m0 = blockIdx.y * 128;
    const int n0 = blockIdx.x * 256;

    const int nIter = Kd >> 6;

    auto issue = [&](int it, int st) {
        const uint32_t sb = sm0 + st * STAGE_BYTES;
        const int kb = it * 64;
        const long long ga_off = GA ? ((long long)(kb >> 9) * ((long long)M_ * D_) + (kb & 511))
                                    : 0;
        #pragma unroll
        for (int i = 0; i < 4; i++) {
            int ci = tid + i * 256;          // 0..1023
            int row = ci >> 3;               // 0..127
            int kc8 = ci & 7;
            uint32_t doff = row * 128 + ((kc8 * 16) ^ ((row & 7) << 4));
            const __half* sa;
            if (GA) sa = Ah + ga_off + (long long)(m0 + row) * D_ + kc8 * 8;
            else    sa = Ah + (long long)(m0 + row) * Kd + kb + kc8 * 8;
            cp16(sb + doff, sa);
        }
        #pragma unroll
        for (int i = 0; i < 8; i++) {
            int ci = tid + i * 256;          // 0..2047
            int row = ci >> 3;               // 0..255
            int kc8 = ci & 7;
            uint32_t doff = row * 128 + ((kc8 * 16) ^ ((row & 7) << 4));
            cp16(sb + 16384 + doff, Bh + (long long)(n0 + row) * Kd + kb + kc8 * 8);
        }
    };

    float acc[4][8][4];
    #pragma unroll
    for (int i = 0; i < 4; i++)
        #pragma unroll
        for (int j = 0; j < 8; j++)
            #pragma unroll
            for (int r = 0; r < 4; r++) acc[i][j][r] = 0.0f;

    issue(0, 0); CP_COMMIT();
    issue(1, 1); CP_COMMIT();
    issue(2, 2); CP_COMMIT();

    const int arow_l = wm * 64 + (lane & 15);
    const int akch   = (lane >> 4) << 4;
    const int brow_l = wn * 64 + ((lane >> 4) << 3) + (lane & 7);
    const int bkch   = ((lane >> 3) & 1) << 4;

    // double-buffered register fragments
    uint32_t ah[2][4][4], bh[2][4][4];

    auto load_frags = [&](uint32_t sb, int kc, int buf) {
        #pragma unroll
        for (int mf = 0; mf < 4; mf++) {
            int row = arow_l + mf * 16;
            uint32_t addr = sb + row * 128 + ((kc * 32 + akch) ^ ((row & 7) << 4));
            ldsm4(ah[buf][mf], addr);
        }
        #pragma unroll
        for (int ng = 0; ng < 4; ng++) {
            int row = brow_l + ng * 16;
            uint32_t addr = sb + 16384 + row * 128 +
                            ((kc * 32 + bkch) ^ ((row & 7) << 4));
            ldsm4(bh[buf][ng], addr);
        }
    };

    for (int it = 0; it < nIter; it++) {
        const int st = it & 3;
        CP_WAIT2();
        __syncthreads();
        // issue next stage immediately after barrier: target stage (it+3)&3
        // was last read in iter it-1, and every warp passed this barrier
        // after those reads.  (Must stay after CP_WAIT2 to keep <=2 pending.)
        if (it + 3 < nIter) issue(it + 3, (it + 3) & 3);
        CP_COMMIT();

        const uint32_t sb = sm0 + st * STAGE_BYTES;
        load_frags(sb, 0, 0);
        #pragma unroll
        for (int kc = 0; kc < 4; kc++) {
            const int cur = kc & 1;
            if (kc < 3) load_frags(sb, kc + 1, cur ^ 1);
            #pragma unroll
            for (int mf = 0; mf < 4; mf++)
                #pragma unroll
                for (int nf = 0; nf < 8; nf++) {
                    const int ng = nf >> 1, j = nf & 1;
                    mma16816(acc[mf][nf], ah[cur][mf],
                             bh[cur][ng][2 * j], bh[cur][ng][2 * j + 1]);
                }
        }
    }

    // ---- epilogue ----
    const int g   = lane >> 2;
    const int cp2 = (lane & 3) * 2;
    #pragma unroll
    for (int mf = 0; mf < 4; mf++) {
        #pragma unroll
        for (int nf = 0; nf < 8; nf++) {
            int row0 = m0 + wm * 64 + mf * 16 + g;
            int row1 = row0 + 8;
            int col  = n0 + wn * 64 + nf * 8 + cp2;
            float v00 = acc[mf][nf][0] * alpha;
            float v01 = acc[mf][nf][1] * alpha;
            float v10 = acc[mf][nf][2] * alpha;
            float v11 = acc[mf][nf][3] * alpha;
            if (bptr) {
                float b0 = bptr[col], b1 = bptr[col + 1];
                v00 += b0; v01 += b1; v10 += b0; v11 += b1;
            }
            if (EPI == 0) {
                *reinterpret_cast<float2*>(Cf + coff + (long long)row0 * Nd + col) =
                    make_float2(v00, v01);
                *reinterpret_cast<float2*>(Cf + coff + (long long)row1 * Nd + col) =
                    make_float2(v10, v11);
            } else if (EPI == 2) {
                Ch[coff + (long long)col * Md + row0]       = __float2half_rn(v00);
                Ch[coff + (long long)(col + 1) * Md + row0] = __float2half_rn(v01);
                Ch[coff + (long long)col * Md + row1]       = __float2half_rn(v10);
                Ch[coff + (long long)(col + 1) * Md + row1] = __float2half_rn(v11);
            } else {  // EPI == 3: fp16 row-major
                __half2 hh0; hh0.x = __float2half_rn(v00); hh0.y = __float2half_rn(v01);
                __half2 hh1; hh1.x = __float2half_rn(v10); hh1.y = __float2half_rn(v11);
                *reinterpret_cast<__half2*>(Ch + coff + (long long)row0 * Nd + col) = hh0;
                *reinterpret_cast<__half2*>(Ch + coff + (long long)row1 * Nd + col) = hh1;
            }
        }
    }
}

// -------------------------------------------------------------------------
// fp32 -> fp16 convert (elementwise)
// -------------------------------------------------------------------------
__global__ void __launch_bounds__(256) convert_h_kernel(
    const float* __restrict__ src, __half* __restrict__ hi, size_t n4)
{
    size_t i = (size_t)blockIdx.x * 256 + threadIdx.x;
    if (i >= n4) return;
    float4 v = reinterpret_cast<const float4*>(src)[i];
    __half2 ha; ha.x = __float2half_rn(v.x); ha.y = __float2half_rn(v.y);
    __half2 hb; hb.x = __float2half_rn(v.z); hb.y = __float2half_rn(v.w);
    reinterpret_cast<__half2*>(hi)[2 * i]     = ha;
    reinterpret_cast<__half2*>(hi)[2 * i + 1] = hb;
}

// -------------------------------------------------------------------------
// Batched transpose: dst[z][c][r] = fp16(src[z][r][c])
// -------------------------------------------------------------------------
__global__ void __launch_bounds__(256) transpose_h_kernel(
    const float* __restrict__ src, __half* __restrict__ hi, int R, int C)
{
    __shared__ float t[32][33];
    const size_t zoff = (size_t)blockIdx.z * R * C;
    int tx = threadIdx.x, ty = threadIdx.y;
    int x = blockIdx.x * 32 + tx;
    int y = blockIdx.y * 32 + ty;
    #pragma unroll
    for (int j = 0; j < 32; j += 8)
        t[ty + j][tx] = src[zoff + (size_t)(y + j) * C + x];
    __syncthreads();
    int x2 = blockIdx.y * 32 + tx;
    int y2 = blockIdx.x * 32 + ty;
    #pragma unroll
    for (int j = 0; j < 32; j += 8)
        hi[zoff + (size_t)(y2 + j) * R + x2] = __float2half_rn(t[tx][ty + j]);
}

// -------------------------------------------------------------------------
// Wo permute+transpose: out[n][k = h*512+d] = fp16(Wo[d*8+h][n])
// -------------------------------------------------------------------------
__global__ void __launch_bounds__(256) wo_permute_h_kernel(
    const float* __restrict__ Wo, __half* __restrict__ hi)
{
    __shared__ float t[32][33];
    int tx = threadIdx.x, ty = threadIdx.y;       // 32 x 8
    int kb = blockIdx.x * 32;
    int nb = blockIdx.y * 32;
    int h  = kb >> 9;
    int d0 = kb & 511;
    #pragma unroll
    for (int j = 0; j < 32; j += 8) {
        int d = d0 + ty + j;
        t[ty + j][tx] = Wo[(size_t)(d * 8 + h) * D_ + nb + tx];
    }
    __syncthreads();
    #pragma unroll
    for (int j = 0; j < 32; j += 8) {
        int n = nb + ty + j;
        hi[(size_t)n * HD_ + kb + tx] = __float2half_rn(t[tx][ty + j]);
    }
}

// -------------------------------------------------------------------------
// Row softmax over N_=2048, emits fp16 probability array.
// -------------------------------------------------------------------------
__global__ void __launch_bounds__(256) softmax_kernel(
    const float* __restrict__ S, __half* __restrict__ Ph)
{
    const long long roff = (long long)blockIdx.x * N_;
    const float* p = S + roff;
    const int tid = threadIdx.x;

    float4 v0 = *reinterpret_cast<const float4*>(p + tid * 8);
    float4 v1 = *reinterpret_cast<const float4*>(p + tid * 8 + 4);

    float m = fmaxf(fmaxf(fmaxf(v0.x, v0.y), fmaxf(v0.z, v0.w)),
                    fmaxf(fmaxf(v1.x, v1.y), fmaxf(v1.z, v1.w)));
    #pragma unroll
    for (int o = 16; o > 0; o >>= 1)
        m = fmaxf(m, __shfl_xor_sync(0xffffffffu, m, o));

    __shared__ float smax[8];
    __shared__ float ssum[8];
    if ((tid & 31) == 0) smax[tid >> 5] = m;
    __syncthreads();
    m = smax[0];
    #pragma unroll
    for (int i = 1; i < 8; i++) m = fmaxf(m, smax[i]);

    v0.x = __expf(v0.x - m); v0.y = __expf(v0.y - m);
    v0.z = __expf(v0.z - m); v0.w = __expf(v0.w - m);
    v1.x = __expf(v1.x - m); v1.y = __expf(v1.y - m);
    v1.z = __expf(v1.z - m); v1.w = __expf(v1.w - m);

    float s = v0.x + v0.y + v0.z + v0.w + v1.x + v1.y + v1.z + v1.w;
    #pragma unroll
    for (int o = 16; o > 0; o >>= 1)
        s += __shfl_xor_sync(0xffffffffu, s, o);
    if ((tid & 31) == 0) ssum[tid >> 5] = s;
    __syncthreads();
    s = 0.0f;
    #pragma unroll
    for (int i = 0; i < 8; i++) s += ssum[i];

    const float inv = 1.0f / s;
    __half2 hh[4];
    hh[0].x = __float2half_rn(v0.x * inv); hh[0].y = __float2half_rn(v0.y * inv);
    hh[1].x = __float2half_rn(v0.z * inv); hh[1].y = __float2half_rn(v0.w * inv);
    hh[2].x = __float2half_rn(v1.x * inv); hh[2].y = __float2half_rn(v1.y * inv);
    hh[3].x = __float2half_rn(v1.z * inv); hh[3].y = __float2half_rn(v1.w * inv);
    *reinterpret_cast<uint4*>(Ph + roff + tid * 8) = *reinterpret_cast<uint4*>(hh);
}

// -------------------------------------------------------------------------
// Launch
// -------------------------------------------------------------------------
extern "C" void kernel_launch(void* const* d_in, const int* in_sizes, int n_in,
                              void* d_out, int out_size)
{
    (void)in_sizes; (void)n_in; (void)out_size;
    const float* k  = (const float*)d_in[0];
    const float* v  = (const float*)d_in[1];
    const float* q  = (const float*)d_in[2];
    const float* Wk = (const float*)d_in[3];
    const float* bk = (const float*)d_in[4];
    const float* Wv = (const float*)d_in[5];
    const float* bv = (const float*)d_in[6];
    const float* Wq = (const float*)d_in[7];
    const float* bq = (const float*)d_in[8];
    const float* Wo = (const float*)d_in[9];
    const float* bo = (const float*)d_in[10];
    float* out = (float*)d_out;

    __half *kc_hi, *vc_hi, *qc_hi;
    __half *WkT_hi, *WvT_hi, *WqT_hi, *WoP_hi;
    __half *kp_hi, *qp_hi, *vT_hi, *P_hi, *at_hi;
    float *sc;
    cudaGetSymbolAddress((void**)&kc_hi, g_kc_hi);
    cudaGetSymbolAddress((void**)&vc_hi, g_vc_hi);
    cudaGetSymbolAddress((void**)&qc_hi, g_qc_hi);
    cudaGetSymbolAddress((void**)&WkT_hi, g_WkT_hi);
    cudaGetSymbolAddress((void**)&WvT_hi, g_WvT_hi);
    cudaGetSymbolAddress((void**)&WqT_hi, g_WqT_hi);
    cudaGetSymbolAddress((void**)&WoP_hi, g_WoP_hi);
    cudaGetSymbolAddress((void**)&kp_hi, g_kp_hi);
    cudaGetSymbolAddress((void**)&qp_hi, g_qp_hi);
    cudaGetSymbolAddress((void**)&vT_hi, g_vT_hi);
    cudaGetSymbolAddress((void**)&P_hi, g_P_hi);
    cudaGetSymbolAddress((void**)&at_hi, g_at_hi);
    cudaGetSymbolAddress((void**)&sc, g_scores);

    const long long sND = (long long)N_ * D_;
    const long long sDD = (long long)D_ * D_;
    const long long sMN = (long long)M_ * N_;
    const long long sMD = (long long)M_ * D_;
    const long long sAB = (long long)H_ * M_ * D_;   // attn batch stride

    cudaFuncSetAttribute(hgemm_kernel<0, false>, cudaFuncAttributeMaxDynamicSharedMemorySize, SHM_TOTAL);
    cudaFuncSetAttribute(hgemm_kernel<2, false>, cudaFuncAttributeMaxDynamicSharedMemorySize, SHM_TOTAL);
    cudaFuncSetAttribute(hgemm_kernel<3, false>, cudaFuncAttributeMaxDynamicSharedMemorySize, SHM_TOTAL);
    cudaFuncSetAttribute(hgemm_kernel<0, true>,  cudaFuncAttributeMaxDynamicSharedMemorySize, SHM_TOTAL);

    // 0) convert inputs + weights to fp16
    {
        size_t n4 = (size_t)B_ * N_ * D_ / 4;
        int gb = (int)((n4 + 255) / 256);
        convert_h_kernel<<<gb, 256>>>(k, kc_hi, n4);
        convert_h_kernel<<<gb, 256>>>(v, vc_hi, n4);
        convert_h_kernel<<<gb, 256>>>(q, qc_hi, n4);
        dim3 tb(32, 8);
        transpose_h_kernel<<<dim3(D_ / 32, D_ / 32, H_), tb>>>(Wk, WkT_hi, D_, D_);
        transpose_h_kernel<<<dim3(D_ / 32, D_ / 32, H_), tb>>>(Wv, WvT_hi, D_, D_);
        transpose_h_kernel<<<dim3(D_ / 32, D_ / 32, H_), tb>>>(Wq, WqT_hi, D_, D_);
        wo_permute_h_kernel<<<dim3(HD_ / 32, D_ / 32), tb>>>(Wo, WoP_hi);
    }

    // 1) projections (1-pass)
    {
        dim3 grid(D_ / 256, N_ / 128, BH_);
        hgemm_kernel<3, false><<<grid, 256, SHM_TOTAL>>>(kc_hi, WkT_hi,
            nullptr, kp_hi, N_, D_, D_, H_, H_, sND, sDD, sND, 1.0f, bk, D_);
        hgemm_kernel<3, false><<<grid, 256, SHM_TOTAL>>>(qc_hi, WqT_hi,
            nullptr, qp_hi, M_, D_, D_, H_, H_, sND, sDD, sND, 1.0f, bq, D_);
        hgemm_kernel<2, false><<<grid, 256, SHM_TOTAL>>>(vc_hi, WvT_hi,
            nullptr, vT_hi, N_, D_, D_, H_, H_, sND, sDD, sND, 1.0f, bv, D_);
    }

    // 2) scores = (q' @ k'^T) / sqrt(D)
    {
        dim3 grid(N_ / 256, M_ / 128, BH_);
        const float scale = 0.044194173824159216f;
        hgemm_kernel<0, false><<<grid, 256, SHM_TOTAL>>>(qp_hi, kp_hi,
            sc, nullptr, M_, N_, D_, 1, BH_, sMD, sND, sMN, scale, nullptr, 0);
    }

    // 3) softmax -> P
    softmax_kernel<<<BH_ * M_, 256>>>(sc, P_hi);

    // 4) attn = P @ v'  -> fp16, layout [z][m][d]
    {
        dim3 grid(D_ / 256, M_ / 128, BH_);
        hgemm_kernel<3, false><<<grid, 256, SHM_TOTAL>>>(P_hi, vT_hi,
            nullptr, at_hi, M_, D_, N_, 1, BH_, sMN, sND, sMD, 1.0f, nullptr, 0);
    }

    // 5) out = attn(gathered, k = h*512+d) @ WoP + bo
    {
        dim3 grid(D_ / 256, M_ / 128, B_);
        hgemm_kernel<0, true><<<grid, 256, SHM_TOTAL>>>(at_hi, WoP_hi,
            out, nullptr, M_, D_, HD_, 1, 1, sAB, 0, sMD, 1.0f, bo, 0);
    }
}

// round 17
// speedup vs baseline: 1.4913x; 1.4913x over previous
#include <cuda_runtime.h>
#include <cuda_fp16.h>
#include <cstdint>

#define B_  8
#define N_  2048
#define M_  2048
#define D_  512
#define H_  8
#define BH_ (B_ * H_)
#define HD_ (H_ * D_)

// -------------------------------------------------------------------------
// Device scratch — all GEMM operands fp16 hi-only (1-pass scheme).
// -------------------------------------------------------------------------
__device__ __half g_kc_hi[(size_t)B_ * N_ * D_];
__device__ __half g_vc_hi[(size_t)B_ * N_ * D_];
__device__ __half g_qc_hi[(size_t)B_ * M_ * D_];
__device__ __half g_WkT_hi[(size_t)H_ * D_ * D_];
__device__ __half g_WvT_hi[(size_t)H_ * D_ * D_];
__device__ __half g_WqT_hi[(size_t)H_ * D_ * D_];
__device__ __half g_WoP_hi[(size_t)D_ * HD_];        // [n=512][k=h*512+d]
__device__ __half g_kp_hi[(size_t)BH_ * N_ * D_];    // k'
__device__ __half g_qp_hi[(size_t)BH_ * M_ * D_];    // q'
__device__ __half g_vT_hi[(size_t)BH_ * D_ * N_];    // v'^T
__device__ float  g_scores[(size_t)BH_ * M_ * N_];
__device__ __half g_P_hi[(size_t)BH_ * M_ * N_];     // softmax probs
__device__ __half g_at_hi[(size_t)BH_ * M_ * D_];    // attn out [z][m][d]

// -------------------------------------------------------------------------
// PTX helpers (family-baseline instructions only)
// -------------------------------------------------------------------------
__device__ __forceinline__ uint32_t smem_to_u32(const void* p) {
    uint32_t a;
    asm("{ .reg .u64 t; cvta.to.shared.u64 t, %1; cvt.u32.u64 %0, t; }" : "=r"(a) : "l"(p));
    return a;
}
__device__ __forceinline__ void cp16(uint32_t dst, const void* src) {
    asm volatile("cp.async.cg.shared.global [%0], [%1], 16;" :: "r"(dst), "l"(src));
}
#define CP_COMMIT() asm volatile("cp.async.commit_group;" ::: "memory")
#define CP_WAIT2()  asm volatile("cp.async.wait_group 2;" ::: "memory")

__device__ __forceinline__ void ldsm4(uint32_t* r, uint32_t addr) {
    asm volatile("ldmatrix.sync.aligned.m8n8.x4.shared.b16 {%0,%1,%2,%3}, [%4];"
                 : "=r"(r[0]), "=r"(r[1]), "=r"(r[2]), "=r"(r[3]) : "r"(addr));
}
__device__ __forceinline__ void mma16816(float* c, const uint32_t* a,
                                         uint32_t b0, uint32_t b1) {
    asm volatile("mma.sync.aligned.m16n8k16.row.col.f32.f16.f16.f32 "
                 "{%0,%1,%2,%3}, {%4,%5,%6,%7}, {%8,%9}, {%0,%1,%2,%3};"
                 : "+f"(c[0]), "+f"(c[1]), "+f"(c[2]), "+f"(c[3])
                 : "r"(a[0]), "r"(a[1]), "r"(a[2]), "r"(a[3]), "r"(b0), "r"(b1));
}

// -------------------------------------------------------------------------
// 1-pass fp16 tensor-core GEMM.  C[z] = alpha * A[z] @ B[z]^T (+ bias)
// A: [Md, Kd] fp16 row-major.  B: [Nd, Kd] fp16 K-major.
// EPI: 0 = fp32 out; 2 = fp16 transposed out (C[n*Md+m]); 3 = fp16 row-major.
// GA:  gather A from attention layout [h][m][d], k = h*512 + d.
// CTA tile 128(M) x 256(N), BK=64, 256 threads (2x4 warps), warp tile 64x64.
// 4-stage cp.async ring, lookahead 3, ONE __syncthreads per iteration;
// next-stage cp.async issued right after the barrier so the loads overlap
// the compute block.  Single-buffer fragments (register-feasibility limit:
// 128 fp32 accumulators leave no room for fragment double-buffering).
// Stage = A(16K) + B(32K) = 48KB; 4 stages = 192KB.
// -------------------------------------------------------------------------
#define STAGE_BYTES 49152u
#define SHM_TOTAL   (4 * 49152)

template <int EPI, bool GA>
__global__ void __launch_bounds__(256, 1) hgemm_kernel(
    const __half* __restrict__ Ah, const __half* __restrict__ Bh,
    float* __restrict__ Cf, __half* __restrict__ Ch,
    int Md, int Nd, int Kd, int divA, int modB,
    long long strideA, long long strideB, long long strideC,
    float alpha, const float* __restrict__ bias, int biasStride)
{
    extern __shared__ char smem[];
    const uint32_t sm0 = smem_to_u32(smem);
    const int tid = threadIdx.x;
    const int wid = tid >> 5, lane = tid & 31;
    const int wm = wid >> 2, wn = wid & 3;           // 2(M) x 4(N) warp grid

    const int z = blockIdx.z;
    Ah += (long long)(z / divA) * strideA;
    Bh += (long long)(z % modB) * strideB;
    const long long coff = (long long)z * strideC;
    const float* bptr = bias ? (bias + (long long)(z % modB) * biasStride) : nullptr;
    const int m0 = blockIdx.y * 128;
    const int n0 = blockIdx.x * 256;

    const int nIter = Kd >> 6;

    auto issue = [&](int it, int st) {
        const uint32_t sb = sm0 + st * STAGE_BYTES;
        const int kb = it * 64;
        const long long ga_off = GA ? ((long long)(kb >> 9) * ((long long)M_ * D_) + (kb & 511))
                                    : 0;
        #pragma unroll
        for (int i = 0; i < 4; i++) {
            int ci = tid + i * 256;          // 0..1023
            int row = ci >> 3;               // 0..127
            int kc8 = ci & 7;
            uint32_t doff = row * 128 + ((kc8 * 16) ^ ((row & 7) << 4));
            const __half* sa;
            if (GA) sa = Ah + ga_off + (long long)(m0 + row) * D_ + kc8 * 8;
            else    sa = Ah + (long long)(m0 + row) * Kd + kb + kc8 * 8;
            cp16(sb + doff, sa);
        }
        #pragma unroll
        for (int i = 0; i < 8; i++) {
            int ci = tid + i * 256;          // 0..2047
            int row = ci >> 3;               // 0..255
            int kc8 = ci & 7;
            uint32_t doff = row * 128 + ((kc8 * 16) ^ ((row & 7) << 4));
            cp16(sb + 16384 + doff, Bh + (long long)(n0 + row) * Kd + kb + kc8 * 8);
        }
    };

    float acc[4][8][4];
    #pragma unroll
    for (int i = 0; i < 4; i++)
        #pragma unroll
        for (int j = 0; j < 8; j++)
            #pragma unroll
            for (int r = 0; r < 4; r++) acc[i][j][r] = 0.0f;

    issue(0, 0); CP_COMMIT();
    issue(1, 1); CP_COMMIT();
    issue(2, 2); CP_COMMIT();

    const int arow_l = wm * 64 + (lane & 15);
    const int akch   = (lane >> 4) << 4;
    const int brow_l = wn * 64 + ((lane >> 4) << 3) + (lane & 7);
    const int bkch   = ((lane >> 3) & 1) << 4;

    for (int it = 0; it < nIter; it++) {
        const int st = it & 3;
        CP_WAIT2();
        __syncthreads();
        // issue next stage right after the barrier: target stage (it+3)&3
        // was last read in iter it-1, and every warp passed this barrier
        // after those reads.  (Stays after CP_WAIT2 -> <=2 pending groups.)
        if (it + 3 < nIter) issue(it + 3, (it + 3) & 3);
        CP_COMMIT();

        const uint32_t sb = sm0 + st * STAGE_BYTES;
        #pragma unroll
        for (int kc = 0; kc < 4; kc++) {
            uint32_t ah[4][4], bh[4][4];
            #pragma unroll
            for (int mf = 0; mf < 4; mf++) {
                int row = arow_l + mf * 16;
                uint32_t addr = sb + row * 128 + ((kc * 32 + akch) ^ ((row & 7) << 4));
                ldsm4(ah[mf], addr);
            }
            #pragma unroll
            for (int ng = 0; ng < 4; ng++) {
                int row = brow_l + ng * 16;
                uint32_t addr = sb + 16384 + row * 128 +
                                ((kc * 32 + bkch) ^ ((row & 7) << 4));
                ldsm4(bh[ng], addr);
            }
            #pragma unroll
            for (int mf = 0; mf < 4; mf++)
                #pragma unroll
                for (int nf = 0; nf < 8; nf++) {
                    const int ng = nf >> 1, j = nf & 1;
                    mma16816(acc[mf][nf], ah[mf], bh[ng][2 * j], bh[ng][2 * j + 1]);
                }
        }
    }

    // ---- epilogue ----
    const int g   = lane >> 2;
    const int cp2 = (lane & 3) * 2;
    #pragma unroll
    for (int mf = 0; mf < 4; mf++) {
        #pragma unroll
        for (int nf = 0; nf < 8; nf++) {
            int row0 = m0 + wm * 64 + mf * 16 + g;
            int row1 = row0 + 8;
            int col  = n0 + wn * 64 + nf * 8 + cp2;
            float v00 = acc[mf][nf][0] * alpha;
            float v01 = acc[mf][nf][1] * alpha;
            float v10 = acc[mf][nf][2] * alpha;
            float v11 = acc[mf][nf][3] * alpha;
            if (bptr) {
                float b0 = bptr[col], b1 = bptr[col + 1];
                v00 += b0; v01 += b1; v10 += b0; v11 += b1;
            }
            if (EPI == 0) {
                *reinterpret_cast<float2*>(Cf + coff + (long long)row0 * Nd + col) =
                    make_float2(v00, v01);
                *reinterpret_cast<float2*>(Cf + coff + (long long)row1 * Nd + col) =
                    make_float2(v10, v11);
            } else if (EPI == 2) {
                Ch[coff + (long long)col * Md + row0]       = __float2half_rn(v00);
                Ch[coff + (long long)(col + 1) * Md + row0] = __float2half_rn(v01);
                Ch[coff + (long long)col * Md + row1]       = __float2half_rn(v10);
                Ch[coff + (long long)(col + 1) * Md + row1] = __float2half_rn(v11);
            } else {  // EPI == 3: fp16 row-major
                __half2 hh0; hh0.x = __float2half_rn(v00); hh0.y = __float2half_rn(v01);
                __half2 hh1; hh1.x = __float2half_rn(v10); hh1.y = __float2half_rn(v11);
                *reinterpret_cast<__half2*>(Ch + coff + (long long)row0 * Nd + col) = hh0;
                *reinterpret_cast<__half2*>(Ch + coff + (long long)row1 * Nd + col) = hh1;
            }
        }
    }
}

// -------------------------------------------------------------------------
// fp32 -> fp16 convert (elementwise)
// -------------------------------------------------------------------------
__global__ void __launch_bounds__(256) convert_h_kernel(
    const float* __restrict__ src, __half* __restrict__ hi, size_t n4)
{
    size_t i = (size_t)blockIdx.x * 256 + threadIdx.x;
    if (i >= n4) return;
    float4 v = reinterpret_cast<const float4*>(src)[i];
    __half2 ha; ha.x = __float2half_rn(v.x); ha.y = __float2half_rn(v.y);
    __half2 hb; hb.x = __float2half_rn(v.z); hb.y = __float2half_rn(v.w);
    reinterpret_cast<__half2*>(hi)[2 * i]     = ha;
    reinterpret_cast<__half2*>(hi)[2 * i + 1] = hb;
}

// -------------------------------------------------------------------------
// Batched transpose: dst[z][c][r] = fp16(src[z][r][c])
// -------------------------------------------------------------------------
__global__ void __launch_bounds__(256) transpose_h_kernel(
    const float* __restrict__ src, __half* __restrict__ hi, int R, int C)
{
    __shared__ float t[32][33];
    const size_t zoff = (size_t)blockIdx.z * R * C;
    int tx = threadIdx.x, ty = threadIdx.y;
    int x = blockIdx.x * 32 + tx;
    int y = blockIdx.y * 32 + ty;
    #pragma unroll
    for (int j = 0; j < 32; j += 8)
        t[ty + j][tx] = src[zoff + (size_t)(y + j) * C + x];
    __syncthreads();
    int x2 = blockIdx.y * 32 + tx;
    int y2 = blockIdx.x * 32 + ty;
    #pragma unroll
    for (int j = 0; j < 32; j += 8)
        hi[zoff + (size_t)(y2 + j) * R + x2] = __float2half_rn(t[tx][ty + j]);
}

// -------------------------------------------------------------------------
// Wo permute+transpose: out[n][k = h*512+d] = fp16(Wo[d*8+h][n])
// -------------------------------------------------------------------------
__global__ void __launch_bounds__(256) wo_permute_h_kernel(
    const float* __restrict__ Wo, __half* __restrict__ hi)
{
    __shared__ float t[32][33];
    int tx = threadIdx.x, ty = threadIdx.y;       // 32 x 8
    int kb = blockIdx.x * 32;
    int nb = blockIdx.y * 32;
    int h  = kb >> 9;
    int d0 = kb & 511;
    #pragma unroll
    for (int j = 0; j < 32; j += 8) {
        int d = d0 + ty + j;
        t[ty + j][tx] = Wo[(size_t)(d * 8 + h) * D_ + nb + tx];
    }
    __syncthreads();
    #pragma unroll
    for (int j = 0; j < 32; j += 8) {
        int n = nb + ty + j;
        hi[(size_t)n * HD_ + kb + tx] = __float2half_rn(t[tx][ty + j]);
    }
}

// -------------------------------------------------------------------------
// Row softmax over N_=2048, emits fp16 probability array.
// -------------------------------------------------------------------------
__global__ void __launch_bounds__(256) softmax_kernel(
    const float* __restrict__ S, __half* __restrict__ Ph)
{
    const long long roff = (long long)blockIdx.x * N_;
    const float* p = S + roff;
    const int tid = threadIdx.x;

    float4 v0 = *reinterpret_cast<const float4*>(p + tid * 8);
    float4 v1 = *reinterpret_cast<const float4*>(p + tid * 8 + 4);

    float m = fmaxf(fmaxf(fmaxf(v0.x, v0.y), fmaxf(v0.z, v0.w)),
                    fmaxf(fmaxf(v1.x, v1.y), fmaxf(v1.z, v1.w)));
    #pragma unroll
    for (int o = 16; o > 0; o >>= 1)
        m = fmaxf(m, __shfl_xor_sync(0xffffffffu, m, o));

    __shared__ float smax[8];
    __shared__ float ssum[8];
    if ((tid & 31) == 0) smax[tid >> 5] = m;
    __syncthreads();
    m = smax[0];
    #pragma unroll
    for (int i = 1; i < 8; i++) m = fmaxf(m, smax[i]);

    v0.x = __expf(v0.x - m); v0.y = __expf(v0.y - m);
    v0.z = __expf(v0.z - m); v0.w = __expf(v0.w - m);
    v1.x = __expf(v1.x - m); v1.y = __expf(v1.y - m);
    v1.z = __expf(v1.z - m); v1.w = __expf(v1.w - m);

    float s = v0.x + v0.y + v0.z + v0.w + v1.x + v1.y + v1.z + v1.w;
    #pragma unroll
    for (int o = 16; o > 0; o >>= 1)
        s += __shfl_xor_sync(0xffffffffu, s, o);
    if ((tid & 31) == 0) ssum[tid >> 5] = s;
    __syncthreads();
    s = 0.0f;
    #pragma unroll
    for (int i = 0; i < 8; i++) s += ssum[i];

    const float inv = 1.0f / s;
    __half2 hh[4];
    hh[0].x = __float2half_rn(v0.x * inv); hh[0].y = __float2half_rn(v0.y * inv);
    hh[1].x = __float2half_rn(v0.z * inv); hh[1].y = __float2half_rn(v0.w * inv);
    hh[2].x = __float2half_rn(v1.x * inv); hh[2].y = __float2half_rn(v1.y * inv);
    hh[3].x = __float2half_rn(v1.z * inv); hh[3].y = __float2half_rn(v1.w * inv);
    *reinterpret_cast<uint4*>(Ph + roff + tid * 8) = *reinterpret_cast<uint4*>(hh);
}

// -------------------------------------------------------------------------
// Launch
// -------------------------------------------------------------------------
extern "C" void kernel_launch(void* const* d_in, const int* in_sizes, int n_in,
                              void* d_out, int out_size)
{
    (void)in_sizes; (void)n_in; (void)out_size;
    const float* k  = (const float*)d_in[0];
    const float* v  = (const float*)d_in[1];
    const float* q  = (const float*)d_in[2];
    const float* Wk = (const float*)d_in[3];
    const float* bk = (const float*)d_in[4];
    const float* Wv = (const float*)d_in[5];
    const float* bv = (const float*)d_in[6];
    const float* Wq = (const float*)d_in[7];
    const float* bq = (const float*)d_in[8];
    const float* Wo = (const float*)d_in[9];
    const float* bo = (const float*)d_in[10];
    float* out = (float*)d_out;

    __half *kc_hi, *vc_hi, *qc_hi;
    __half *WkT_hi, *WvT_hi, *WqT_hi, *WoP_hi;
    __half *kp_hi, *qp_hi, *vT_hi, *P_hi, *at_hi;
    float *sc;
    cudaGetSymbolAddress((void**)&kc_hi, g_kc_hi);
    cudaGetSymbolAddress((void**)&vc_hi, g_vc_hi);
    cudaGetSymbolAddress((void**)&qc_hi, g_qc_hi);
    cudaGetSymbolAddress((void**)&WkT_hi, g_WkT_hi);
    cudaGetSymbolAddress((void**)&WvT_hi, g_WvT_hi);
    cudaGetSymbolAddress((void**)&WqT_hi, g_WqT_hi);
    cudaGetSymbolAddress((void**)&WoP_hi, g_WoP_hi);
    cudaGetSymbolAddress((void**)&kp_hi, g_kp_hi);
    cudaGetSymbolAddress((void**)&qp_hi, g_qp_hi);
    cudaGetSymbolAddress((void**)&vT_hi, g_vT_hi);
    cudaGetSymbolAddress((void**)&P_hi, g_P_hi);
    cudaGetSymbolAddress((void**)&at_hi, g_at_hi);
    cudaGetSymbolAddress((void**)&sc, g_scores);

    const long long sND = (long long)N_ * D_;
    const long long sDD = (long long)D_ * D_;
    const long long sMN = (long long)M_ * N_;
    const long long sMD = (long long)M_ * D_;
    const long long sAB = (long long)H_ * M_ * D_;   // attn batch stride

    cudaFuncSetAttribute(hgemm_kernel<0, false>, cudaFuncAttributeMaxDynamicSharedMemorySize, SHM_TOTAL);
    cudaFuncSetAttribute(hgemm_kernel<2, false>, cudaFuncAttributeMaxDynamicSharedMemorySize, SHM_TOTAL);
    cudaFuncSetAttribute(hgemm_kernel<3, false>, cudaFuncAttributeMaxDynamicSharedMemorySize, SHM_TOTAL);
    cudaFuncSetAttribute(hgemm_kernel<0, true>,  cudaFuncAttributeMaxDynamicSharedMemorySize, SHM_TOTAL);

    // 0) convert inputs + weights to fp16
    {
        size_t n4 = (size_t)B_ * N_ * D_ / 4;
        int gb = (int)((n4 + 255) / 256);
        convert_h_kernel<<<gb, 256>>>(k, kc_hi, n4);
        convert_h_kernel<<<gb, 256>>>(v, vc_hi, n4);
        convert_h_kernel<<<gb, 256>>>(q, qc_hi, n4);
        dim3 tb(32, 8);
        transpose_h_kernel<<<dim3(D_ / 32, D_ / 32, H_), tb>>>(Wk, WkT_hi, D_, D_);
        transpose_h_kernel<<<dim3(D_ / 32, D_ / 32, H_), tb>>>(Wv, WvT_hi, D_, D_);
        transpose_h_kernel<<<dim3(D_ / 32, D_ / 32, H_), tb>>>(Wq, WqT_hi, D_, D_);
        wo_permute_h_kernel<<<dim3(HD_ / 32, D_ / 32), tb>>>(Wo, WoP_hi);
    }

    // 1) projections (1-pass)
    {
        dim3 grid(D_ / 256, N_ / 128, BH_);
        hgemm_kernel<3, false><<<grid, 256, SHM_TOTAL>>>(kc_hi, WkT_hi,
            nullptr, kp_hi, N_, D_, D_, H_, H_, sND, sDD, sND, 1.0f, bk, D_);
        hgemm_kernel<3, false><<<grid, 256, SHM_TOTAL>>>(qc_hi, WqT_hi,
            nullptr, qp_hi, M_, D_, D_, H_, H_, sND, sDD, sND, 1.0f, bq, D_);
        hgemm_kernel<2, false><<<grid, 256, SHM_TOTAL>>>(vc_hi, WvT_hi,
            nullptr, vT_hi, N_, D_, D_, H_, H_, sND, sDD, sND, 1.0f, bv, D_);
    }

    // 2) scores = (q' @ k'^T) / sqrt(D)
    {
        dim3 grid(N_ / 256, M_ / 128, BH_);
        const float scale = 0.044194173824159216f;
        hgemm_kernel<0, false><<<grid, 256, SHM_TOTAL>>>(qp_hi, kp_hi,
            sc, nullptr, M_, N_, D_, 1, BH_, sMD, sND, sMN, scale, nullptr, 0);
    }

    // 3) softmax -> P
    softmax_kernel<<<BH_ * M_, 256>>>(sc, P_hi);

    // 4) attn = P @ v'  -> fp16, layout [z][m][d]
    {
        dim3 grid(D_ / 256, M_ / 128, BH_);
        hgemm_kernel<3, false><<<grid, 256, SHM_TOTAL>>>(P_hi, vT_hi,
            nullptr, at_hi, M_, D_, N_, 1, BH_, sMN, sND, sMD, 1.0f, nullptr, 0);
    }

    // 5) out = attn(gathered, k = h*512+d) @ WoP + bo
    {
        dim3 grid(D_ / 256, M_ / 128, B_);
        hgemm_kernel<0, true><<<grid, 256, SHM_TOTAL>>>(at_hi, WoP_hi,
            out, nullptr, M_, D_, HD_, 1, 1, sAB, 0, sMD, 1.0f, bo, 0);
    }
}